// round 2
// baseline (speedup 1.0000x reference)
#include <cuda_runtime.h>
#include <cstddef>

#define NN 2048
#define FF 32
#define EE 16
#define KK 32

// Scratch (allocation-free rule: __device__ globals)
__device__ float g_node_part[NN * FF];  // nodes @ W_ne[:F]
__device__ float g_node_term[NN * FF];  // relu(nodes @ W_n + b_n)

// ---------------------------------------------------------------------------
// Kernel 1: per-node precompute. 8 rows per 256-thread block.
// ---------------------------------------------------------------------------
__global__ void gin_precompute(const float* __restrict__ nodes,
                               const float* __restrict__ W_ne,
                               const float* __restrict__ W_n,
                               const float* __restrict__ b_n) {
    __shared__ float sWne[FF * FF];
    __shared__ float sWn[FF * FF];
    const int tid = threadIdx.x;
    for (int t = tid; t < FF * FF; t += 256) {
        sWne[t] = W_ne[t];   // first F rows of W_ne
        sWn[t]  = W_n[t];
    }
    __syncthreads();

    const int f   = tid & 31;
    const int r   = tid >> 5;                 // 0..7
    const int row = blockIdx.x * 8 + r;
    if (row >= NN) return;

    float accp = 0.f;
    float acct = b_n[f];
    const float* nrow = nodes + row * FF;
#pragma unroll
    for (int k = 0; k < FF; k++) {
        const float x = nrow[k];              // broadcast within warp
        accp = fmaf(x, sWne[k * FF + f], accp);
        acct = fmaf(x, sWn[k * FF + f],  acct);
    }
    g_node_part[row * FF + f] = accp;
    g_node_term[row * FF + f] = fmaxf(acct, 0.f);
}

// ---------------------------------------------------------------------------
// Kernel 2: one block per row i. 8 warps scan adj[i,:], copy it to out_adj,
// and for each nonzero j compute relu(node_part[j] + edges[i,j]@W_E + b_ne),
// accumulate msg. Epilogue: (1+eps)*node_term + msg, then @W_net + relu.
// ---------------------------------------------------------------------------
__global__ __launch_bounds__(256) void gin_rows(
        const float* __restrict__ adj,
        const float* __restrict__ edges,
        const float* __restrict__ W_ne,   // rows F..F+E used
        const float* __restrict__ b_ne,
        const float* __restrict__ W_net,
        const float* __restrict__ b_net,
        const float* __restrict__ eps_p,
        float* __restrict__ out_adj,
        float* __restrict__ out_net) {
    const int i    = blockIdx.x;
    const int tid  = threadIdx.x;
    const int lane = tid & 31;
    const int warp = tid >> 5;            // 0..7

    __shared__ float sWE[EE * FF];        // edge half of W_ne
    __shared__ float sWnet[FF * KK];
    __shared__ float smsg[8][FF];
    __shared__ float smid[FF];

    for (int t = tid; t < EE * FF; t += 256) sWE[t]   = W_ne[FF * FF + t];
    for (int t = tid; t < FF * KK; t += 256) sWnet[t] = W_net[t];
    __syncthreads();

    const float bne = b_ne[lane];
    float msg = 0.f;

    const size_t rowbase = (size_t)i * NN;
    const float* adj_row = adj + rowbase;
    float* oadj_row = out_adj + rowbase;

    for (int j0 = warp * 32; j0 < NN; j0 += 8 * 32) {
        const float a = adj_row[j0 + lane];
        oadj_row[j0 + lane] = a;                       // fused adj copy
        unsigned m = __ballot_sync(0xffffffffu, a != 0.f);
        while (m) {
            const int b = __ffs(m) - 1;
            m &= m - 1;
            const int j = j0 + b;
            const float aval = __shfl_sync(0xffffffffu, a, b);
            const float* ep = edges + ((size_t)(rowbase + j)) * EE;
            const float ev = (lane < EE) ? ep[lane] : 0.f;
            float acc = 0.f;
#pragma unroll
            for (int e = 0; e < EE; e++)
                acc = fmaf(__shfl_sync(0xffffffffu, ev, e),
                           sWE[e * FF + lane], acc);
            const float v = g_node_part[j * FF + lane] + acc + bne;
            msg = fmaf(aval, fmaxf(v, 0.f), msg);
        }
    }

    smsg[warp][lane] = msg;
    __syncthreads();

    if (warp == 0) {
        float mtot = 0.f;
#pragma unroll
        for (int w = 0; w < 8; w++) mtot += smsg[w][lane];
        const float eps = eps_p[0];
        const float mid = (1.f + eps) * g_node_term[i * FF + lane] + mtot;
        smid[lane] = mid;
        __syncwarp();
        float acc = b_net[lane];
#pragma unroll
        for (int f = 0; f < FF; f++)
            acc = fmaf(smid[f], sWnet[f * KK + lane], acc);
        out_net[i * KK + lane] = fmaxf(acc, 0.f);
    }
}

// ---------------------------------------------------------------------------
// kernel_launch — inputs per metadata order:
// adj, nodes_features, edges_features, W_ne, b_ne, W_n, b_n, W_net, b_net, eps
// Output tuple flattened: [adj (N*N), out (N*K), edges_features (N*N*E)]
// ---------------------------------------------------------------------------
extern "C" void kernel_launch(void* const* d_in, const int* in_sizes, int n_in,
                              void* d_out, int out_size) {
    const float* adj    = (const float*)d_in[0];
    const float* nodes  = (const float*)d_in[1];
    const float* edges  = (const float*)d_in[2];
    const float* W_ne   = (const float*)d_in[3];
    const float* b_ne   = (const float*)d_in[4];
    const float* W_n    = (const float*)d_in[5];
    const float* b_n    = (const float*)d_in[6];
    const float* W_net  = (const float*)d_in[7];
    const float* b_net  = (const float*)d_in[8];
    const float* eps    = (const float*)d_in[9];

    float* out       = (float*)d_out;
    float* out_adj   = out;
    float* out_net   = out + (size_t)NN * NN;
    float* out_edges = out + (size_t)NN * NN + (size_t)NN * KK;

    // Bulk edges copy (268 MB) — driver D2D copy, near-peak HBM.
    cudaMemcpyAsync(out_edges, edges,
                    (size_t)NN * NN * EE * sizeof(float),
                    cudaMemcpyDeviceToDevice);

    gin_precompute<<<NN / 8, 256>>>(nodes, W_ne, W_n, b_n);
    gin_rows<<<NN, 256>>>(adj, edges, W_ne, b_ne, W_net, b_net, eps,
                          out_adj, out_net);
}

// round 6
// speedup vs baseline: 1.0918x; 1.0918x over previous
#include <cuda_runtime.h>
#include <cstddef>

#define NN 2048
#define FF 32
#define EE 16
#define KK 32

// Scratch (allocation-free rule: __device__ globals)
__device__ float g_node_part[NN * FF];  // nodes @ W_ne[:F]
__device__ float g_node_term[NN * FF];  // relu(nodes @ W_n + b_n)

// ---------------------------------------------------------------------------
// Kernel 1: per-node precompute. 8 rows per 256-thread block. (~2 us)
// ---------------------------------------------------------------------------
__global__ void gin_precompute(const float* __restrict__ nodes,
                               const float* __restrict__ W_ne,
                               const float* __restrict__ W_n,
                               const float* __restrict__ b_n) {
    __shared__ float sWne[FF * FF];
    __shared__ float sWn[FF * FF];
    const int tid = threadIdx.x;
    for (int t = tid; t < FF * FF; t += 256) {
        sWne[t] = W_ne[t];   // first F rows of W_ne
        sWn[t]  = W_n[t];
    }
    __syncthreads();

    const int f   = tid & 31;
    const int r   = tid >> 5;                 // 0..7
    const int row = blockIdx.x * 8 + r;
    if (row >= NN) return;

    float accp = 0.f;
    float acct = b_n[f];
    const float* nrow = nodes + row * FF;
#pragma unroll
    for (int k = 0; k < FF; k++) {
        const float x = nrow[k];              // broadcast within warp
        accp = fmaf(x, sWne[k * FF + f], accp);
        acct = fmaf(x, sWn[k * FF + f],  acct);
    }
    g_node_part[row * FF + f] = accp;
    g_node_term[row * FF + f] = fmaxf(acct, 0.f);
}

// ---------------------------------------------------------------------------
// Kernel 2 (FUSED): one block per row i.
//   Phase A: stream-copy edges[i,:,:] (128 KB) via float4  -> out_edges
//   Phase B: scan adj[i,:] (fused copy), sparse message compute; the edge
//            gathers hit L1/L2 since Phase A just pulled the row through.
//   Epilogue: (1+eps)*node_term + msg, @W_net + relu.
// ---------------------------------------------------------------------------
__global__ __launch_bounds__(256) void gin_fused(
        const float* __restrict__ adj,
        const float* __restrict__ edges,
        const float* __restrict__ W_ne,   // rows F..F+E used
        const float* __restrict__ b_ne,
        const float* __restrict__ W_net,
        const float* __restrict__ b_net,
        const float* __restrict__ eps_p,
        float* __restrict__ out_adj,
        float* __restrict__ out_net,
        float* __restrict__ out_edges) {
    const int i    = blockIdx.x;
    const int tid  = threadIdx.x;
    const int lane = tid & 31;
    const int warp = tid >> 5;            // 0..7

    __shared__ float sWE[EE * FF];        // edge half of W_ne
    __shared__ float sWnet[FF * KK];
    __shared__ float smsg[8][FF];
    __shared__ float smid[FF];

    for (int t = tid; t < EE * FF; t += 256) sWE[t]   = W_ne[FF * FF + t];
    for (int t = tid; t < FF * KK; t += 256) sWnet[t] = W_net[t];
    __syncthreads();

    const size_t rowbase = (size_t)i * NN;

    // ---- Phase A: copy this row's edge block (NN*EE floats = 8192 float4) ----
    {
        const float4* __restrict__ esrc =
            (const float4*)(edges + rowbase * EE);
        float4* __restrict__ edst = (float4*)(out_edges + rowbase * EE);
        constexpr int NV = NN * EE / 4;   // 8192
#pragma unroll 4
        for (int t = tid; t < NV; t += 256) {
            edst[t] = esrc[t];
        }
    }

    // ---- Phase B: sparse message accumulation + adj copy ----
    const float bne = b_ne[lane];
    float msg = 0.f;

    const float* adj_row = adj + rowbase;
    float* oadj_row = out_adj + rowbase;

    for (int j0 = warp * 32; j0 < NN; j0 += 8 * 32) {
        const float a = adj_row[j0 + lane];
        oadj_row[j0 + lane] = a;                       // fused adj copy
        unsigned m = __ballot_sync(0xffffffffu, a != 0.f);
        while (m) {
            const int b = __ffs(m) - 1;
            m &= m - 1;
            const int j = j0 + b;
            const float aval = __shfl_sync(0xffffffffu, a, b);
            const float* ep = edges + (rowbase + (size_t)j) * EE;
            const float ev = (lane < EE) ? ep[lane] : 0.f;   // L1/L2 hit (Phase A)
            float acc = 0.f;
#pragma unroll
            for (int e = 0; e < EE; e++)
                acc = fmaf(__shfl_sync(0xffffffffu, ev, e),
                           sWE[e * FF + lane], acc);
            const float v = g_node_part[j * FF + lane] + acc + bne;
            msg = fmaf(aval, fmaxf(v, 0.f), msg);
        }
    }

    smsg[warp][lane] = msg;
    __syncthreads();

    if (warp == 0) {
        float mtot = 0.f;
#pragma unroll
        for (int w = 0; w < 8; w++) mtot += smsg[w][lane];
        const float eps = eps_p[0];
        const float mid = (1.f + eps) * g_node_term[i * FF + lane] + mtot;
        smid[lane] = mid;
        __syncwarp();
        float acc = b_net[lane];
#pragma unroll
        for (int f = 0; f < FF; f++)
            acc = fmaf(smid[f], sWnet[f * KK + lane], acc);
        out_net[i * KK + lane] = fmaxf(acc, 0.f);
    }
}

// ---------------------------------------------------------------------------
// kernel_launch — inputs per metadata order:
// adj, nodes_features, edges_features, W_ne, b_ne, W_n, b_n, W_net, b_net, eps
// Output tuple flattened: [adj (N*N), out (N*K), edges_features (N*N*E)]
// ---------------------------------------------------------------------------
extern "C" void kernel_launch(void* const* d_in, const int* in_sizes, int n_in,
                              void* d_out, int out_size) {
    const float* adj    = (const float*)d_in[0];
    const float* nodes  = (const float*)d_in[1];
    const float* edges  = (const float*)d_in[2];
    const float* W_ne   = (const float*)d_in[3];
    const float* b_ne   = (const float*)d_in[4];
    const float* W_n    = (const float*)d_in[5];
    const float* b_n    = (const float*)d_in[6];
    const float* W_net  = (const float*)d_in[7];
    const float* b_net  = (const float*)d_in[8];
    const float* eps    = (const float*)d_in[9];

    float* out       = (float*)d_out;
    float* out_adj   = out;
    float* out_net   = out + (size_t)NN * NN;
    float* out_edges = out + (size_t)NN * NN + (size_t)NN * KK;

    gin_precompute<<<NN / 8, 256>>>(nodes, W_ne, W_n, b_n);
    gin_fused<<<NN, 256>>>(adj, edges, W_ne, b_ne, W_net, b_net, eps,
                           out_adj, out_net, out_edges);
}